// round 4
// baseline (speedup 1.0000x reference)
#include <cuda_runtime.h>
#include <math.h>

// Problem constants
#define BATCH 2
#define SEQ   2048
#define NEMBD 1024
#define HEADS 16
#define HDIM  64
#define BH    (BATCH * HEADS)

typedef unsigned long long u64;

// ---------------------------------------------------------------------------
// Packed f32x2 helpers (SASS FFMA2 path — only reachable via PTX)
// ---------------------------------------------------------------------------
__device__ __forceinline__ u64 pk2(float lo, float hi) {
    u64 r; asm("mov.b64 %0, {%1, %2};" : "=l"(r) : "f"(lo), "f"(hi)); return r;
}
__device__ __forceinline__ void upk2(u64 v, float& lo, float& hi) {
    asm("mov.b64 {%0, %1}, %2;" : "=f"(lo), "=f"(hi) : "l"(v));
}
__device__ __forceinline__ u64 fma2(u64 a, u64 b, u64 c) {
    u64 d; asm("fma.rn.f32x2 %0, %1, %2, %3;" : "=l"(d) : "l"(a), "l"(b), "l"(c)); return d;
}
__device__ __forceinline__ u64 mul2(u64 a, u64 b) {
    u64 d; asm("mul.rn.f32x2 %0, %1, %2;" : "=l"(d) : "l"(a), "l"(b)); return d;
}
// Raw 2^x (softmax domain is pre-scaled by log2e at the QKV projection)
__device__ __forceinline__ float ex2(float x) {
    float y; asm("ex2.approx.ftz.f32 %0, %1;" : "=f"(y) : "f"(x)); return y;
}

// ---------------------------------------------------------------------------
// Scratch (device globals: no allocations allowed). Layout: [B*H][T][HDIM]
// ---------------------------------------------------------------------------
__device__ float g_Q[(size_t)BH * SEQ * HDIM];
__device__ float g_K[(size_t)BH * SEQ * HDIM];
__device__ float g_V[(size_t)BH * SEQ * HDIM];

// ===========================================================================
// Kernel 1: QKV projection GEMM (f32x2 math, pairs along N)
//   qkv[m, n] = x[m, :] @ W[:, n] + b[n],  m in [0, 4096), n in [0, 3072)
//   Scatter into g_Q / g_K / g_V head-major; Q pre-scaled 0.125*log2(e) so
//   the attention softmax can use raw ex2.
//   Tiles: 128x128x16, 256 threads, 8x8 micro-tile, double-buffered smem.
// ===========================================================================
#define GBM 128
#define GBN 128
#define GBK 16
#define GK  NEMBD              // 1024
#define GN  (3 * NEMBD)        // 3072
#define GM  (BATCH * SEQ)      // 4096

#define QSCALE (0.125f * 1.44269504088896340736f)   // (1/sqrt(64)) * log2(e)

__global__ __launch_bounds__(256, 2)
void qkv_gemm_kernel(const float* __restrict__ x,
                     const float* __restrict__ W,
                     const float* __restrict__ bias)
{
    // strides (GBM+4)=132 floats = 528 B (multiple of 16 -> ull2 loads legal)
    __shared__ __align__(16) float As[2][GBK][GBM + 4];
    __shared__ __align__(16) float Bs[2][GBK][GBN + 4];

    const int tid = threadIdx.x;
    const int tx  = tid & 15;       // 0..15  -> 8 cols each
    const int ty  = tid >> 4;       // 0..15  -> 8 rows each
    const int m0  = blockIdx.y * GBM;
    const int n0  = blockIdx.x * GBN;

    // A: 128x16 tile = 512 float4 -> 2 per thread (float4 along K)
    const int aRow0 = tid >> 2;            const int aK0 = (tid & 3) * 4;
    const int aRow1 = (tid + 256) >> 2;    const int aK1 = ((tid + 256) & 3) * 4;
    // B: 16x128 tile = 512 float4 -> 2 per thread (float4 along N)
    const int bRow0 = tid >> 5;            const int bN0 = (tid & 31) * 4;
    const int bRow1 = (tid + 256) >> 5;    const int bN1 = ((tid + 256) & 31) * 4;

    float4 a0, a1, b0, b1;

    auto loadTile = [&](int kt) {
        const int kb = kt * GBK;
        a0 = *(const float4*)(x + (size_t)(m0 + aRow0) * GK + kb + aK0);
        a1 = *(const float4*)(x + (size_t)(m0 + aRow1) * GK + kb + aK1);
        b0 = *(const float4*)(W + (size_t)(kb + bRow0) * GN + n0 + bN0);
        b1 = *(const float4*)(W + (size_t)(kb + bRow1) * GN + n0 + bN1);
    };
    auto storeTile = [&](int buf) {
        As[buf][aK0 + 0][aRow0] = a0.x;  As[buf][aK0 + 1][aRow0] = a0.y;
        As[buf][aK0 + 2][aRow0] = a0.z;  As[buf][aK0 + 3][aRow0] = a0.w;
        As[buf][aK1 + 0][aRow1] = a1.x;  As[buf][aK1 + 1][aRow1] = a1.y;
        As[buf][aK1 + 2][aRow1] = a1.z;  As[buf][aK1 + 3][aRow1] = a1.w;
        *(float4*)&Bs[buf][bRow0][bN0] = b0;
        *(float4*)&Bs[buf][bRow1][bN1] = b1;
    };

    // Accumulators: 8 rows x 4 column-pairs (cols 2jp, 2jp+1), packed f32x2
    u64 accp[8][4];
    #pragma unroll
    for (int i = 0; i < 8; ++i)
        #pragma unroll
        for (int jp = 0; jp < 4; ++jp) accp[i][jp] = 0ull;

    loadTile(0);
    storeTile(0);
    __syncthreads();

    const int NKT = GK / GBK;   // 64
    for (int kt = 0; kt < NKT; ++kt) {
        const int cur = kt & 1;
        if (kt + 1 < NKT) loadTile(kt + 1);

        #pragma unroll
        for (int k = 0; k < GBK; ++k) {
            float4 qa0 = *(const float4*)&As[cur][k][ty * 8];
            float4 qa1 = *(const float4*)&As[cur][k][ty * 8 + 4];
            // B pairs come straight from LDS.128 (contiguous along N)
            ulonglong2 qb0 = *(const ulonglong2*)&Bs[cur][k][tx * 8];
            ulonglong2 qb1 = *(const ulonglong2*)&Bs[cur][k][tx * 8 + 4];
            u64 bp[4] = {qb0.x, qb0.y, qb1.x, qb1.y};
            float a[8] = {qa0.x, qa0.y, qa0.z, qa0.w, qa1.x, qa1.y, qa1.z, qa1.w};
            #pragma unroll
            for (int i = 0; i < 8; ++i) {
                const u64 ap = pk2(a[i], a[i]);
                #pragma unroll
                for (int jp = 0; jp < 4; ++jp)
                    accp[i][jp] = fma2(ap, bp[jp], accp[i][jp]);
            }
        }

        if (kt + 1 < NKT) {
            storeTile(cur ^ 1);
            __syncthreads();
        }
    }

    // Unpack accumulators
    float acc[8][8];
    #pragma unroll
    for (int i = 0; i < 8; ++i)
        #pragma unroll
        for (int jp = 0; jp < 4; ++jp)
            upk2(accp[i][jp], acc[i][2 * jp], acc[i][2 * jp + 1]);

    // Epilogue: add bias, scale Q, scatter into head-major Q/K/V.
    // The 8 columns of a row are consecutive and stay inside one 64-wide head
    // (tx*8 mod 64 <= 56), so writes vectorize to 2x STG.128 per row.
    const int part = n0 >> 10;                 // whole block is within one of Q/K/V
    float* dst = (part == 0) ? g_Q : (part == 1) ? g_K : g_V;
    const float qscale = (part == 0) ? QSCALE : 1.0f;

    const int colBase = n0 + tx * 8;
    const float4 bi0 = __ldg((const float4*)(bias + colBase));
    const float4 bi1 = __ldg((const float4*)(bias + colBase + 4));
    const int cc = colBase & (NEMBD - 1);
    const int h  = cc >> 6;
    const int d0 = cc & (HDIM - 1);            // multiple of 8

    #pragma unroll
    for (int i = 0; i < 8; ++i) {
        const int m  = m0 + ty * 8 + i;        // global row = b*SEQ + t
        const int bb = m >> 11;                // /2048
        const int t  = m & (SEQ - 1);
        float* p = dst + ((size_t)(bb * HEADS + h) * SEQ + t) * HDIM + d0;
        float4 v0, v1;
        v0.x = (acc[i][0] + bi0.x) * qscale;
        v0.y = (acc[i][1] + bi0.y) * qscale;
        v0.z = (acc[i][2] + bi0.z) * qscale;
        v0.w = (acc[i][3] + bi0.w) * qscale;
        v1.x = (acc[i][4] + bi1.x) * qscale;
        v1.y = (acc[i][5] + bi1.y) * qscale;
        v1.z = (acc[i][6] + bi1.z) * qscale;
        v1.w = (acc[i][7] + bi1.w) * qscale;
        *(float4*)p       = v0;
        *(float4*)(p + 4) = v1;
    }
}

// ===========================================================================
// Kernel 2: causal flash attention, fp32 with f32x2 math
//   Per block: one (b,h) and a 128-query tile. Loop 64-key tiles, online
//   softmax in log2 domain (Q pre-scaled by log2e -> raw ex2).
//   256 threads (16x16), 8x4 micro-tile, accumulators packed along row-pairs
//   (Qst/Pst transposed layouts are row-contiguous -> paired operand comes
//   straight from LDS.128). K/V tiles software-pipelined through registers.
// ===========================================================================
#define ABM 128
#define ABN 64
#define QS  (ABM + 4)   // 132 floats = 528 B stride (16B multiple)
#define KS  (ABN + 4)   // 68 floats  = 272 B stride (16B multiple)

#define ATTN_SMEM ((64 * QS + 64 * KS + 64 * KS + 64 * QS) * 4)   // 102400 B

__global__ __launch_bounds__(256, 2)
void attn_kernel(float* __restrict__ out)
{
    extern __shared__ __align__(16) float sm[];
    float* Qst = sm;                         // [64][QS]  Q^T : [d][r]
    float* Kst = Qst + 64 * QS;              // [64][KS]  K^T : [d][c]
    float* Vs  = Kst + 64 * KS;              // [64][KS]  V   : [c][d]
    float* Pst = Vs  + 64 * KS;              // [64][QS]  P^T : [c][r]

    const int tid = threadIdx.x;
    const int tx  = tid & 15;                // 4 cols each
    const int ty  = tid >> 4;                // 8 rows each
    const int bh  = blockIdx.y;
    const int qt  = gridDim.x - 1 - blockIdx.x;   // big tiles first

    const float* Qp = g_Q + (size_t)bh * SEQ * HDIM + (size_t)qt * ABM * HDIM;
    const float* Kp = g_K + (size_t)bh * SEQ * HDIM;
    const float* Vp = g_V + (size_t)bh * SEQ * HDIM;

    // Per-thread K/V staging slots (4 float4 each: 64x64 tile / 256 threads)
    const int cA  = tid >> 4;                // slot w covers row cA + w*16
    const int dqA = (tid & 15) * 4;

    float4 pk[4], pv[4];

    auto ldKV = [&](int kt) {
        #pragma unroll
        for (int w = 0; w < 4; ++w) {
            const int c = cA + w * 16;
            const size_t g = ((size_t)kt * ABN + c) * HDIM + dqA;
            pk[w] = *(const float4*)(Kp + g);
            pv[w] = *(const float4*)(Vp + g);
        }
    };
    auto stKV = [&]() {
        #pragma unroll
        for (int w = 0; w < 4; ++w) {
            const int c = cA + w * 16;
            Kst[(dqA + 0) * KS + c] = pk[w].x;
            Kst[(dqA + 1) * KS + c] = pk[w].y;
            Kst[(dqA + 2) * KS + c] = pk[w].z;
            Kst[(dqA + 3) * KS + c] = pk[w].w;
            *(float4*)(Vs + c * KS + dqA) = pv[w];
        }
    };

    // Load 128x64 Q tile, transposed into Qst[d][r]
    #pragma unroll
    for (int w = 0; w < 8; ++w) {
        const int lin = tid + w * 256;       // float4 index, 2048 total
        const int r   = lin >> 4;
        const int dq  = (lin & 15) * 4;
        float4 v = *(const float4*)(Qp + (size_t)r * HDIM + dq);
        Qst[(dq + 0) * QS + r] = v.x;
        Qst[(dq + 1) * QS + r] = v.y;
        Qst[(dq + 2) * QS + r] = v.z;
        Qst[(dq + 3) * QS + r] = v.w;
    }

    float mrow[8], lrow[8];
    u64 op[4][4];                            // O accum: 4 row-pairs x 4 dims
    #pragma unroll
    for (int i = 0; i < 8; ++i) { mrow[i] = -1e30f; lrow[i] = 0.0f; }
    #pragma unroll
    for (int ip = 0; ip < 4; ++ip)
        #pragma unroll
        for (int j = 0; j < 4; ++j) op[ip][j] = 0ull;

    const int nkt = 2 * qt + 2;              // causal: keys up to end of q tile
    ldKV(0);                                 // prefetch tile 0

    for (int kt = 0; kt < nkt; ++kt) {
        __syncthreads();   // prev PV done (Kst/Vs/Pst free); Q stores visible
        stKV();            // commit prefetched K/V tile to smem
        if (kt + 1 < nkt) ldKV(kt + 1);      // issue next tile's LDGs early
        __syncthreads();

        // S = Q K^T  (per-thread 8x4, packed as 4 row-pairs x 4 cols)
        u64 sp[4][4];
        #pragma unroll
        for (int ip = 0; ip < 4; ++ip)
            #pragma unroll
            for (int j = 0; j < 4; ++j) sp[ip][j] = 0ull;

        #pragma unroll 8
        for (int k = 0; k < 64; ++k) {
            // Q row-pairs straight from LDS.128 (rows contiguous in Qst)
            ulonglong2 q01 = *(const ulonglong2*)(Qst + k * QS + ty * 8);
            ulonglong2 q23 = *(const ulonglong2*)(Qst + k * QS + ty * 8 + 4);
            u64 qp[4] = {q01.x, q01.y, q23.x, q23.y};
            float4 kk = *(const float4*)(Kst + k * KS + tx * 4);
            u64 kb[4] = {pk2(kk.x, kk.x), pk2(kk.y, kk.y),
                         pk2(kk.z, kk.z), pk2(kk.w, kk.w)};
            #pragma unroll
            for (int ip = 0; ip < 4; ++ip)
                #pragma unroll
                for (int j = 0; j < 4; ++j)
                    sp[ip][j] = fma2(qp[ip], kb[j], sp[ip][j]);
        }

        // Unpack S for masking + softmax (log2 domain)
        float s[8][4];
        #pragma unroll
        for (int ip = 0; ip < 4; ++ip)
            #pragma unroll
            for (int j = 0; j < 4; ++j)
                upk2(sp[ip][j], s[2 * ip][j], s[2 * ip + 1][j]);

        // Causal mask (only the two diagonal key tiles need it)
        if (kt >= 2 * qt) {
            #pragma unroll
            for (int i = 0; i < 8; ++i) {
                const int qr = qt * ABM + ty * 8 + i;
                #pragma unroll
                for (int j = 0; j < 4; ++j) {
                    const int kc = kt * ABN + tx * 4 + j;
                    if (kc > qr) s[i][j] = -1e30f;
                }
            }
        }

        // Online softmax (2^x domain): row reductions over the 16 tx lanes
        float scale[8];
        #pragma unroll
        for (int i = 0; i < 8; ++i) {
            float mx = s[i][0];
            mx = fmaxf(mx, s[i][1]); mx = fmaxf(mx, s[i][2]); mx = fmaxf(mx, s[i][3]);
            #pragma unroll
            for (int off = 8; off > 0; off >>= 1)
                mx = fmaxf(mx, __shfl_xor_sync(0xffffffffu, mx, off));
            const float mn = fmaxf(mrow[i], mx);
            scale[i] = ex2(mrow[i] - mn);
            mrow[i] = mn;
            float rs = 0.0f;
            #pragma unroll
            for (int j = 0; j < 4; ++j) {
                const float p = ex2(s[i][j] - mn);
                s[i][j] = p;
                rs += p;
            }
            #pragma unroll
            for (int off = 8; off > 0; off >>= 1)
                rs += __shfl_xor_sync(0xffffffffu, rs, off);
            lrow[i] = lrow[i] * scale[i] + rs;
        }

        // Rescale O accumulators (packed per row-pair)
        #pragma unroll
        for (int ip = 0; ip < 4; ++ip) {
            const u64 sc = pk2(scale[2 * ip], scale[2 * ip + 1]);
            #pragma unroll
            for (int j = 0; j < 4; ++j) op[ip][j] = mul2(op[ip][j], sc);
        }

        // Stage P transposed for the PV GEMM
        #pragma unroll
        for (int i = 0; i < 8; ++i)
            #pragma unroll
            for (int j = 0; j < 4; ++j)
                Pst[(tx * 4 + j) * QS + ty * 8 + i] = s[i][j];
        __syncthreads();

        // O += P V   (row-pairs packed; P pairs straight from LDS.128)
        #pragma unroll 8
        for (int c = 0; c < 64; ++c) {
            ulonglong2 p01 = *(const ulonglong2*)(Pst + c * QS + ty * 8);
            ulonglong2 p23 = *(const ulonglong2*)(Pst + c * QS + ty * 8 + 4);
            u64 pp[4] = {p01.x, p01.y, p23.x, p23.y};
            float4 vv = *(const float4*)(Vs + c * KS + tx * 4);
            u64 vb[4] = {pk2(vv.x, vv.x), pk2(vv.y, vv.y),
                         pk2(vv.z, vv.z), pk2(vv.w, vv.w)};
            #pragma unroll
            for (int ip = 0; ip < 4; ++ip)
                #pragma unroll
                for (int j = 0; j < 4; ++j)
                    op[ip][j] = fma2(pp[ip], vb[j], op[ip][j]);
        }
    }

    // Epilogue: normalize and write out [B, T, NEMBD]
    const int bb = bh >> 4;
    const int h  = bh & 15;
    #pragma unroll
    for (int ip = 0; ip < 4; ++ip) {
        float olo[4], ohi[4];
        #pragma unroll
        for (int j = 0; j < 4; ++j) upk2(op[ip][j], olo[j], ohi[j]);

        #pragma unroll
        for (int half = 0; half < 2; ++half) {
            const int i = 2 * ip + half;
            const float inv = 1.0f / lrow[i];
            const float* oo = half ? ohi : olo;
            const int trow = qt * ABM + ty * 8 + i;
            float* opn = out + ((size_t)(bb * SEQ + trow)) * NEMBD + h * HDIM + tx * 4;
            float4 v;
            v.x = oo[0] * inv;
            v.y = oo[1] * inv;
            v.z = oo[2] * inv;
            v.w = oo[3] * inv;
            *(float4*)opn = v;
        }
    }
}

// ===========================================================================
// Launch
// ===========================================================================
extern "C" void kernel_launch(void* const* d_in, const int* in_sizes, int n_in,
                              void* d_out, int out_size)
{
    const float* x    = (const float*)d_in[0];   // [2, 2048, 1024]
    const float* Wqkv = (const float*)d_in[1];   // [1024, 3072]
    const float* bqkv = (const float*)d_in[2];   // [3072]
    float* out        = (float*)d_out;           // [2, 2048, 1024]

    (void)in_sizes; (void)n_in; (void)out_size;

    // Idempotent attribute set (no static guards; not a stream op, capture-safe)
    cudaFuncSetAttribute(attn_kernel,
                         cudaFuncAttributeMaxDynamicSharedMemorySize, ATTN_SMEM);

    dim3 g1(GN / GBN, GM / GBM);   // (24, 32)
    qkv_gemm_kernel<<<g1, 256>>>(x, Wqkv, bqkv);

    dim3 g2(SEQ / ABM, BH);        // (16, 32)
    attn_kernel<<<g2, 256, ATTN_SMEM>>>(out);
}

// round 10
// speedup vs baseline: 1.4174x; 1.4174x over previous
#include <cuda_runtime.h>
#include <cuda_bf16.h>
#include <math.h>
#include <stdint.h>

// Problem constants
#define BATCH 2
#define SEQ   2048
#define NEMBD 1024
#define HEADS 16
#define HDIM  64
#define BH    (BATCH * HEADS)

typedef unsigned long long u64;

// ---------------------------------------------------------------------------
// Packed f32x2 helpers (SASS FFMA2 path — only reachable via PTX)
// ---------------------------------------------------------------------------
__device__ __forceinline__ u64 pk2(float lo, float hi) {
    u64 r; asm("mov.b64 %0, {%1, %2};" : "=l"(r) : "f"(lo), "f"(hi)); return r;
}
__device__ __forceinline__ void upk2(u64 v, float& lo, float& hi) {
    asm("mov.b64 {%0, %1}, %2;" : "=f"(lo), "=f"(hi) : "l"(v));
}
__device__ __forceinline__ u64 fma2(u64 a, u64 b, u64 c) {
    u64 d; asm("fma.rn.f32x2 %0, %1, %2, %3;" : "=l"(d) : "l"(a), "l"(b), "l"(c)); return d;
}
__device__ __forceinline__ u64 mul2(u64 a, u64 b) {
    u64 d; asm("mul.rn.f32x2 %0, %1, %2;" : "=l"(d) : "l"(a), "l"(b)); return d;
}
__device__ __forceinline__ float ex2(float x) {
    float y; asm("ex2.approx.ftz.f32 %0, %1;" : "=f"(y) : "f"(x)); return y;
}

// ---------------------------------------------------------------------------
// sm_80-era tensor path (supported on base sm_103 target): mma.sync + ldmatrix
// ---------------------------------------------------------------------------
__device__ __forceinline__ uint32_t smem_u32(const void* p) {
    uint32_t a;
    asm("{ .reg .u64 t; cvta.to.shared.u64 t, %1; cvt.u32.u64 %0, t; }"
        : "=r"(a) : "l"(p));
    return a;
}
__device__ __forceinline__ void ldsm_x4(uint32_t& r0, uint32_t& r1,
                                        uint32_t& r2, uint32_t& r3, uint32_t addr) {
    asm volatile("ldmatrix.sync.aligned.m8n8.x4.shared.b16 {%0,%1,%2,%3}, [%4];"
                 : "=r"(r0), "=r"(r1), "=r"(r2), "=r"(r3) : "r"(addr));
}
__device__ __forceinline__ void mma_bf16(float* d, const uint32_t* a, const uint32_t* b) {
    asm volatile(
        "mma.sync.aligned.m16n8k16.row.col.f32.bf16.bf16.f32 "
        "{%0,%1,%2,%3}, {%4,%5,%6,%7}, {%8,%9}, {%0,%1,%2,%3};"
        : "+f"(d[0]), "+f"(d[1]), "+f"(d[2]), "+f"(d[3])
        : "r"(a[0]), "r"(a[1]), "r"(a[2]), "r"(a[3]), "r"(b[0]), "r"(b[1]));
}
__device__ __forceinline__ void cp_async16(uint32_t dst, const void* src) {
    asm volatile("cp.async.ca.shared.global [%0], [%1], 16;"
                 :: "r"(dst), "l"(src));
}
#define CP_COMMIT() asm volatile("cp.async.commit_group;" ::: "memory")
#define CP_WAIT(n)  asm volatile("cp.async.wait_group %0;" :: "n"(n) : "memory")

// ---------------------------------------------------------------------------
// Scratch (device globals: no allocations allowed)
// ---------------------------------------------------------------------------
__device__ float g_Q[(size_t)BH * SEQ * HDIM];
__device__ float g_K[(size_t)BH * SEQ * HDIM];
__device__ float g_V[(size_t)BH * SEQ * HDIM];
// bf16 hi/lo splits: x [4096][1024], W^T [3072][1024]
__device__ __nv_bfloat16 g_xh[(size_t)4096 * 1024];
__device__ __nv_bfloat16 g_xl[(size_t)4096 * 1024];
__device__ __nv_bfloat16 g_wth[(size_t)3072 * 1024];
__device__ __nv_bfloat16 g_wtl[(size_t)3072 * 1024];

#define GK  NEMBD              // 1024
#define GN  (3 * NEMBD)        // 3072
#define GM  (BATCH * SEQ)      // 4096
#define QSCALE (0.125f * 1.44269504088896340736f)   // (1/sqrt(64)) * log2(e)

// ===========================================================================
// Conversion kernels: fp32 -> bf16 hi/lo split (and W transpose)
// ===========================================================================
__global__ void convert_x_kernel(const float* __restrict__ x)
{
    const size_t i = (size_t)blockIdx.x * blockDim.x + threadIdx.x;   // float4 idx
    const float4 v = ((const float4*)x)[i];
    __nv_bfloat162 h01 = __floats2bfloat162_rn(v.x, v.y);
    __nv_bfloat162 h23 = __floats2bfloat162_rn(v.z, v.w);
    __nv_bfloat162 l01 = __floats2bfloat162_rn(v.x - __low2float(h01),
                                               v.y - __high2float(h01));
    __nv_bfloat162 l23 = __floats2bfloat162_rn(v.z - __low2float(h23),
                                               v.w - __high2float(h23));
    ((__nv_bfloat162*)g_xh)[i * 2 + 0] = h01;
    ((__nv_bfloat162*)g_xh)[i * 2 + 1] = h23;
    ((__nv_bfloat162*)g_xl)[i * 2 + 0] = l01;
    ((__nv_bfloat162*)g_xl)[i * 2 + 1] = l23;
}

__global__ void convert_wt_kernel(const float* __restrict__ W)
{
    __shared__ float tile[32][33];
    const int tx = threadIdx.x;        // 0..31
    const int ty = threadIdx.y;        // 0..7
    const int n0 = blockIdx.x * 32;
    const int k0 = blockIdx.y * 32;

    #pragma unroll
    for (int j = 0; j < 32; j += 8)
        tile[ty + j][tx] = W[(size_t)(k0 + ty + j) * GN + n0 + tx];
    __syncthreads();

    #pragma unroll
    for (int j = 0; j < 32; j += 8) {
        const float v = tile[tx][ty + j];         // = W[k0+tx][n0+ty+j]
        const __nv_bfloat16 h = __float2bfloat16_rn(v);
        const __nv_bfloat16 l = __float2bfloat16_rn(v - __bfloat162float(h));
        const size_t o = (size_t)(n0 + ty + j) * GK + k0 + tx;
        g_wth[o] = h;
        g_wtl[o] = l;
    }
}

// ===========================================================================
// Kernel 1: QKV projection GEMM on HMMA (mma.sync m16n8k16 bf16)
//   3-term split: xh@Wh + xh@Wl + xl@Wh, fp32 register accumulation.
//   CTA 128x128, 8 warps (2x4), warp tile 64x32 (4x4 mma frags).
//   K in 32 chunks of KC=32, cp.async double-buffered smem.
//   Smem rows padded to 40 bf16 (80 B) -> ldmatrix conflict-free.
// ===========================================================================
#define KC 32
#define NCHUNK (GK / KC)       // 32
#define PADK 40                // row stride in bf16 elems (80 B)
#define ROWB (PADK * 2)        // 80 bytes
#define TILE_B (128 * ROWB)    // 10240 B per operand tile
#define BUF_B (4 * TILE_B)     // 40960 B per buffer (Ah, Al, Bh, Bl)
#define OFF_AH 0
#define OFF_AL (1 * TILE_B)
#define OFF_BH (2 * TILE_B)
#define OFF_BL (3 * TILE_B)
#define GEMM_SMEM (2 * BUF_B)  // 81920 B

__global__ __launch_bounds__(256)
void qkv_gemm_mma_kernel(const float* __restrict__ bias)
{
    extern __shared__ char smem_raw[];
    const uint32_t sm0 = smem_u32(smem_raw);

    const int tid  = threadIdx.x;
    const int wid  = tid >> 5;
    const int lane = tid & 31;
    const int wm   = wid >> 2;          // 0..1  -> M offset wm*64
    const int wn   = wid & 3;           // 0..3  -> N offset wn*32
    const int n0   = blockIdx.x * 128;
    const int m0   = blockIdx.y * 128;

    const __nv_bfloat16* srcs[4] = {
        g_xh  + (size_t)m0 * GK,  g_xl  + (size_t)m0 * GK,
        g_wth + (size_t)n0 * GK,  g_wtl + (size_t)n0 * GK };
    const int offs[4] = {OFF_AH, OFF_AL, OFF_BH, OFF_BL};

    // cp.async: per chunk 4 tiles x 128 rows x 4 x 16B segs = 2048 segs
    auto issueChunk = [&](int chunk, int buf) {
        const uint32_t bb = sm0 + buf * BUF_B;
        #pragma unroll
        for (int t = 0; t < 4; ++t) {
            #pragma unroll
            for (int it = 0; it < 2; ++it) {
                const int idx = it * 256 + tid;           // 0..511
                const int row = idx >> 2;                 // 0..127
                const int seg = idx & 3;                  // 16B unit
                const uint32_t dst = bb + offs[t] + row * ROWB + seg * 16;
                const char* src = (const char*)(srcs[t] + (size_t)row * GK + chunk * KC)
                                  + seg * 16;
                cp_async16(dst, src);
            }
        }
        CP_COMMIT();
    };

    float acc[4][4][4];
    #pragma unroll
    for (int mt = 0; mt < 4; ++mt)
        #pragma unroll
        for (int nt = 0; nt < 4; ++nt)
            #pragma unroll
            for (int q = 0; q < 4; ++q) acc[mt][nt][q] = 0.0f;

    issueChunk(0, 0);

    // ldmatrix lane address components (audited against PTX ISA frag layouts)
    const int aRowL = (lane & 15);                 // A: rows m..m+15
    const int aKL   = (lane >> 4) << 3;            // A: +8 k for lanes 16-31
    const int bRowL = (lane & 7) + ((lane & 16) >> 1);   // B: +8 n for lanes>=16
    const int bKL   = (lane & 8);                  // B: +8 k for lanes 8-15/24-31

    for (int chunk = 0; chunk < NCHUNK; ++chunk) {
        const int buf = chunk & 1;
        if (chunk + 1 < NCHUNK) issueChunk(chunk + 1, buf ^ 1);
        if (chunk + 1 < NCHUNK) { CP_WAIT(1); } else { CP_WAIT(0); }
        __syncthreads();

        const uint32_t bb = sm0 + buf * BUF_B;

        #pragma unroll
        for (int ks = 0; ks < 2; ++ks) {
            const int k0 = ks * 16;

            uint32_t aH[4][4], aL[4][4], bH[4][2], bL[4][2];
            #pragma unroll
            for (int mt = 0; mt < 4; ++mt) {
                const int r = wm * 64 + mt * 16 + aRowL;
                const uint32_t ad = bb + r * ROWB + (k0 + aKL) * 2;
                ldsm_x4(aH[mt][0], aH[mt][1], aH[mt][2], aH[mt][3], ad + OFF_AH);
                ldsm_x4(aL[mt][0], aL[mt][1], aL[mt][2], aL[mt][3], ad + OFF_AL);
            }
            #pragma unroll
            for (int ntp = 0; ntp < 2; ++ntp) {
                const int r = wn * 32 + ntp * 16 + bRowL;
                const uint32_t ad = bb + r * ROWB + (k0 + bKL) * 2;
                ldsm_x4(bH[ntp*2][0], bH[ntp*2][1], bH[ntp*2+1][0], bH[ntp*2+1][1],
                        ad + OFF_BH);
                ldsm_x4(bL[ntp*2][0], bL[ntp*2][1], bL[ntp*2+1][0], bL[ntp*2+1][1],
                        ad + OFF_BL);
            }

            #pragma unroll
            for (int mt = 0; mt < 4; ++mt)
                #pragma unroll
                for (int nt = 0; nt < 4; ++nt) {
                    mma_bf16(acc[mt][nt], aH[mt], bH[nt]);
                    mma_bf16(acc[mt][nt], aH[mt], bL[nt]);
                    mma_bf16(acc[mt][nt], aL[mt], bH[nt]);
                }
        }
        __syncthreads();
    }

    // Epilogue: bias + scale, scatter head-major into g_Q/g_K/g_V
    const int part = n0 >> 10;                 // tile never straddles Q/K/V
    float* dst = (part == 0) ? g_Q : (part == 1) ? g_K : g_V;
    const float qscale = (part == 0) ? QSCALE : 1.0f;

    const int lane4 = lane >> 2;
    const int lane2 = (lane & 3) * 2;

    #pragma unroll
    for (int mt = 0; mt < 4; ++mt) {
        #pragma unroll
        for (int nt = 0; nt < 4; ++nt) {
            const int col = n0 + wn * 32 + nt * 8 + lane2;
            const float2 bi = __ldg((const float2*)(bias + col));
            const int cc = col & (NEMBD - 1);
            const int h  = cc >> 6;
            const int d  = cc & (HDIM - 1);

            #pragma unroll
            for (int half = 0; half < 2; ++half) {
                const int m  = m0 + wm * 64 + mt * 16 + lane4 + half * 8;
                const int bb2 = m >> 11;
                const int t   = m & (SEQ - 1);
                float2 v;
                v.x = (acc[mt][nt][half * 2 + 0] + bi.x) * qscale;
                v.y = (acc[mt][nt][half * 2 + 1] + bi.y) * qscale;
                *(float2*)(dst + ((size_t)(bb2 * HEADS + h) * SEQ + t) * HDIM + d) = v;
            }
        }
    }
}

// ===========================================================================
// Kernel 2: causal flash attention, fp32 with f32x2 math (unchanged, passing)
// ===========================================================================
#define ABM 128
#define ABN 64
#define QS  (ABM + 4)
#define KS  (ABN + 4)
#define ATTN_SMEM ((64 * QS + 64 * KS + 64 * KS + 64 * QS) * 4)   // 102400 B

__global__ __launch_bounds__(256, 2)
void attn_kernel(float* __restrict__ out)
{
    extern __shared__ __align__(16) float sm[];
    float* Qst = sm;                         // [64][QS]  Q^T : [d][r]
    float* Kst = Qst + 64 * QS;              // [64][KS]  K^T : [d][c]
    float* Vs  = Kst + 64 * KS;              // [64][KS]  V   : [c][d]
    float* Pst = Vs  + 64 * KS;              // [64][QS]  P^T : [c][r]

    const int tid = threadIdx.x;
    const int tx  = tid & 15;
    const int ty  = tid >> 4;
    const int bh  = blockIdx.y;
    const int qt  = gridDim.x - 1 - blockIdx.x;

    const float* Qp = g_Q + (size_t)bh * SEQ * HDIM + (size_t)qt * ABM * HDIM;
    const float* Kp = g_K + (size_t)bh * SEQ * HDIM;
    const float* Vp = g_V + (size_t)bh * SEQ * HDIM;

    const int cA  = tid >> 4;
    const int dqA = (tid & 15) * 4;

    float4 pk[4], pv[4];

    auto ldKV = [&](int kt) {
        #pragma unroll
        for (int w = 0; w < 4; ++w) {
            const int c = cA + w * 16;
            const size_t g = ((size_t)kt * ABN + c) * HDIM + dqA;
            pk[w] = *(const float4*)(Kp + g);
            pv[w] = *(const float4*)(Vp + g);
        }
    };
    auto stKV = [&]() {
        #pragma unroll
        for (int w = 0; w < 4; ++w) {
            const int c = cA + w * 16;
            Kst[(dqA + 0) * KS + c] = pk[w].x;
            Kst[(dqA + 1) * KS + c] = pk[w].y;
            Kst[(dqA + 2) * KS + c] = pk[w].z;
            Kst[(dqA + 3) * KS + c] = pk[w].w;
            *(float4*)(Vs + c * KS + dqA) = pv[w];
        }
    };

    #pragma unroll
    for (int w = 0; w < 8; ++w) {
        const int lin = tid + w * 256;
        const int r   = lin >> 4;
        const int dq  = (lin & 15) * 4;
        float4 v = *(const float4*)(Qp + (size_t)r * HDIM + dq);
        Qst[(dq + 0) * QS + r] = v.x;
        Qst[(dq + 1) * QS + r] = v.y;
        Qst[(dq + 2) * QS + r] = v.z;
        Qst[(dq + 3) * QS + r] = v.w;
    }

    float mrow[8], lrow[8];
    u64 op[4][4];
    #pragma unroll
    for (int i = 0; i < 8; ++i) { mrow[i] = -1e30f; lrow[i] = 0.0f; }
    #pragma unroll
    for (int ip = 0; ip < 4; ++ip)
        #pragma unroll
        for (int j = 0; j < 4; ++j) op[ip][j] = 0ull;

    const int nkt = 2 * qt + 2;
    ldKV(0);

    for (int kt = 0; kt < nkt; ++kt) {
        __syncthreads();
        stKV();
        if (kt + 1 < nkt) ldKV(kt + 1);
        __syncthreads();

        u64 sp[4][4];
        #pragma unroll
        for (int ip = 0; ip < 4; ++ip)
            #pragma unroll
            for (int j = 0; j < 4; ++j) sp[ip][j] = 0ull;

        #pragma unroll 8
        for (int k = 0; k < 64; ++k) {
            ulonglong2 q01 = *(const ulonglong2*)(Qst + k * QS + ty * 8);
            ulonglong2 q23 = *(const ulonglong2*)(Qst + k * QS + ty * 8 + 4);
            u64 qp[4] = {q01.x, q01.y, q23.x, q23.y};
            float4 kk = *(const float4*)(Kst + k * KS + tx * 4);
            u64 kb[4] = {pk2(kk.x, kk.x), pk2(kk.y, kk.y),
                         pk2(kk.z, kk.z), pk2(kk.w, kk.w)};
            #pragma unroll
            for (int ip = 0; ip < 4; ++ip)
                #pragma unroll
                for (int j = 0; j < 4; ++j)
                    sp[ip][j] = fma2(qp[ip], kb[j], sp[ip][j]);
        }

        float s[8][4];
        #pragma unroll
        for (int ip = 0; ip < 4; ++ip)
            #pragma unroll
            for (int j = 0; j < 4; ++j)
                upk2(sp[ip][j], s[2 * ip][j], s[2 * ip + 1][j]);

        if (kt >= 2 * qt) {
            #pragma unroll
            for (int i = 0; i < 8; ++i) {
                const int qr = qt * ABM + ty * 8 + i;
                #pragma unroll
                for (int j = 0; j < 4; ++j) {
                    const int kc = kt * ABN + tx * 4 + j;
                    if (kc > qr) s[i][j] = -1e30f;
                }
            }
        }

        float scale[8];
        #pragma unroll
        for (int i = 0; i < 8; ++i) {
            float mx = s[i][0];
            mx = fmaxf(mx, s[i][1]); mx = fmaxf(mx, s[i][2]); mx = fmaxf(mx, s[i][3]);
            #pragma unroll
            for (int off = 8; off > 0; off >>= 1)
                mx = fmaxf(mx, __shfl_xor_sync(0xffffffffu, mx, off));
            const float mn = fmaxf(mrow[i], mx);
            scale[i] = ex2(mrow[i] - mn);
            mrow[i] = mn;
            float rs = 0.0f;
            #pragma unroll
            for (int j = 0; j < 4; ++j) {
                const float p = ex2(s[i][j] - mn);
                s[i][j] = p;
                rs += p;
            }
            #pragma unroll
            for (int off = 8; off > 0; off >>= 1)
                rs += __shfl_xor_sync(0xffffffffu, rs, off);
            lrow[i] = lrow[i] * scale[i] + rs;
        }

        #pragma unroll
        for (int ip = 0; ip < 4; ++ip) {
            const u64 sc = pk2(scale[2 * ip], scale[2 * ip + 1]);
            #pragma unroll
            for (int j = 0; j < 4; ++j) op[ip][j] = mul2(op[ip][j], sc);
        }

        #pragma unroll
        for (int i = 0; i < 8; ++i)
            #pragma unroll
            for (int j = 0; j < 4; ++j)
                Pst[(tx * 4 + j) * QS + ty * 8 + i] = s[i][j];
        __syncthreads();

        #pragma unroll 8
        for (int c = 0; c < 64; ++c) {
            ulonglong2 p01 = *(const ulonglong2*)(Pst + c * QS + ty * 8);
            ulonglong2 p23 = *(const ulonglong2*)(Pst + c * QS + ty * 8 + 4);
            u64 pp[4] = {p01.x, p01.y, p23.x, p23.y};
            float4 vv = *(const float4*)(Vs + c * KS + tx * 4);
            u64 vb[4] = {pk2(vv.x, vv.x), pk2(vv.y, vv.y),
                         pk2(vv.z, vv.z), pk2(vv.w, vv.w)};
            #pragma unroll
            for (int ip = 0; ip < 4; ++ip)
                #pragma unroll
                for (int j = 0; j < 4; ++j)
                    op[ip][j] = fma2(pp[ip], vb[j], op[ip][j]);
        }
    }

    const int bb = bh >> 4;
    const int h  = bh & 15;
    #pragma unroll
    for (int ip = 0; ip < 4; ++ip) {
        float olo[4], ohi[4];
        #pragma unroll
        for (int j = 0; j < 4; ++j) upk2(op[ip][j], olo[j], ohi[j]);

        #pragma unroll
        for (int half = 0; half < 2; ++half) {
            const int i = 2 * ip + half;
            const float inv = 1.0f / lrow[i];
            const float* oo = half ? ohi : olo;
            const int trow = qt * ABM + ty * 8 + i;
            float* opn = out + ((size_t)(bb * SEQ + trow)) * NEMBD + h * HDIM + tx * 4;
            float4 v;
            v.x = oo[0] * inv;
            v.y = oo[1] * inv;
            v.z = oo[2] * inv;
            v.w = oo[3] * inv;
            *(float4*)opn = v;
        }
    }
}

// ===========================================================================
// Launch
// ===========================================================================
extern "C" void kernel_launch(void* const* d_in, const int* in_sizes, int n_in,
                              void* d_out, int out_size)
{
    const float* x    = (const float*)d_in[0];   // [2, 2048, 1024]
    const float* Wqkv = (const float*)d_in[1];   // [1024, 3072]
    const float* bqkv = (const float*)d_in[2];   // [3072]
    float* out        = (float*)d_out;           // [2, 2048, 1024]

    (void)in_sizes; (void)n_in; (void)out_size;

    cudaFuncSetAttribute(attn_kernel,
                         cudaFuncAttributeMaxDynamicSharedMemorySize, ATTN_SMEM);
    cudaFuncSetAttribute(qkv_gemm_mma_kernel,
                         cudaFuncAttributeMaxDynamicSharedMemorySize, GEMM_SMEM);

    // bf16 hi/lo splits of x and W^T
    convert_x_kernel<<<(GM * GK / 4) / 256, 256>>>(x);
    convert_wt_kernel<<<dim3(GN / 32, GK / 32), dim3(32, 8)>>>(Wqkv);

    // QKV projection on HMMA tensor path
    qkv_gemm_mma_kernel<<<dim3(GN / 128, GM / 128), 256, GEMM_SMEM>>>(bqkv);

    // attention
    dim3 g2(SEQ / ABM, BH);        // (16, 32)
    attn_kernel<<<g2, 256, ATTN_SMEM>>>(out);
}